// round 12
// baseline (speedup 1.0000x reference)
#include <cuda_runtime.h>
#include <math.h>

// Shapes
#define V_SZ 50257
#define E_SZ 512
#define H_SZ 1024
#define C_SZ 1024
#define S_SZ 2048
#define NRC 16               // row-chunks for wsum partials
#define NBLK 148             // persistent blocks (1 per SM, single wave)
#define TPB 1024

// ---------------- scratch (device globals) --------------------------------------
__device__ __align__(16) float g_x[H_SZ];               // h of layer 0
__device__ __align__(16) float g_q[H_SZ];               // rnn_output
__device__ __align__(16) float g_u[3][C_SZ];            // W^T q per head
__device__            float g_bq[3];                    // b . q per head
__device__ __align__(16) float g_e[3][S_SZ];            // attention logits
__device__ __align__(16) float g_wpart[3][NRC][C_SZ];   // wsum row-chunk partials
__device__ __align__(16) float g_ctx[3][C_SZ];          // reduced attention contexts
__device__ __align__(16) float g_co[H_SZ];              // concat_out

// ---------------- device-wide barrier (sense-reversal, replay-safe) --------------
__device__ unsigned g_barc;
__device__ volatile unsigned g_barg;

__device__ __forceinline__ void gbar() {
    __syncthreads();
    if (threadIdx.x == 0) {
        __threadfence();
        unsigned gen = g_barg;
        if (atomicAdd(&g_barc, 1u) == NBLK - 1) {
            atomicExch(&g_barc, 0u);
            __threadfence();
            g_barg = gen + 1;
        } else {
            while (g_barg == gen) { __nanosleep(64); }
        }
        __threadfence();
    }
    __syncthreads();
}

// ---------------- helpers --------------------------------------------------------
__device__ __forceinline__ float warp_sum(float v) {
#pragma unroll
    for (int o = 16; o; o >>= 1) v += __shfl_xor_sync(0xffffffffu, v, o);
    return v;
}
__device__ __forceinline__ float warp_max(float v) {
#pragma unroll
    for (int o = 16; o; o >>= 1) v = fmaxf(v, __shfl_xor_sync(0xffffffffu, v, o));
    return v;
}
__device__ __forceinline__ float sigf(float x) { return 1.0f / (1.0f + expf(-x)); }
__device__ __forceinline__ float dot4(float4 w, float4 v) {
    return w.x * v.x + w.y * v.y + w.z * v.z + w.w * v.w;
}

// ==================================================================================
__global__ __launch_bounds__(TPB, 1) void megakernel(
    const int* __restrict__ idx,
    const float* __restrict__ h0,  const float* __restrict__ c0,
    const float* __restrict__ ctxL, const float* __restrict__ ctxR,
    const float* __restrict__ ctxM, const float* __restrict__ emb,
    const float* __restrict__ Wih0, const float* __restrict__ Whh0,
    const float* __restrict__ bih0, const float* __restrict__ bhh0,
    const float* __restrict__ Wih1, const float* __restrict__ Whh1,
    const float* __restrict__ bih1, const float* __restrict__ bhh1,
    const float* __restrict__ WL, const float* __restrict__ bL,
    const float* __restrict__ WR, const float* __restrict__ bR,
    const float* __restrict__ WM, const float* __restrict__ bM,
    const float* __restrict__ Wc, const float* __restrict__ bc,
    const float* __restrict__ Wo, const float* __restrict__ bo,
    float* __restrict__ out, float* __restrict__ h_new, float* __restrict__ c_new)
{
    __shared__ __align__(16) float sm[5200];
    const int tid  = threadIdx.x;
    const int wid  = tid >> 5;
    const int lane = tid & 31;
    const int bid  = blockIdx.x;
    const int gw   = bid * 32 + wid;

    // ============ P1: LSTM layer 0 — contiguous 7-row stripe per block ===========
    {
        const float* x = emb + (size_t)idx[0] * E_SZ;
        for (int i = tid; i < E_SZ; i += TPB) sm[i] = x[i];
        for (int i = tid; i < H_SZ; i += TPB) sm[E_SZ + i] = h0[i];
        __syncthreads();

        const int gi = wid >> 3, jj = wid & 7;       // 4 gates x 8 slots (7 used)
        const int j = bid * 7 + jj;
        if (jj < 7 && j < H_SZ) {
            const int row = gi * H_SZ + j;
            const float4* a  = (const float4*)(Wih0 + (size_t)row * E_SZ);
            const float4* b  = (const float4*)(Whh0 + (size_t)row * H_SZ);
            const float4* x4 = (const float4*)sm;
            const float4* h4 = (const float4*)(sm + E_SZ);

            float s = 0.f;
            {
                float4 wv[4];
#pragma unroll
                for (int k = 0; k < 4; k++) wv[k] = a[lane + 32 * k];
#pragma unroll
                for (int k = 0; k < 4; k++) s += dot4(wv[k], x4[lane + 32 * k]);
            }
            {
                float4 wv[8];
#pragma unroll
                for (int k = 0; k < 8; k++) wv[k] = b[lane + 32 * k];
#pragma unroll
                for (int k = 0; k < 8; k++) s += dot4(wv[k], h4[lane + 32 * k]);
            }
            s = warp_sum(s);
            if (lane == 0) sm[1536 + gi * 8 + jj] = s + bih0[row] + bhh0[row];
        }
        __syncthreads();

        if (tid < 7) {
            const int jo = bid * 7 + tid;
            if (jo < H_SZ) {
                const float ig = sigf (sm[1536 + tid]);
                const float fg = sigf (sm[1536 + 8 + tid]);
                const float gg = tanhf(sm[1536 + 16 + tid]);
                const float og = sigf (sm[1536 + 24 + tid]);
                const float c = fg * c0[jo] + ig * gg;
                const float h = og * tanhf(c);
                c_new[jo] = c;
                h_new[jo] = h;
                g_x[jo]  = h;
            }
        }
    }
    gbar();

    // ============ P2: LSTM layer 1 — contiguous 7-row stripe, writes q ===========
    {
        for (int i = tid; i < H_SZ; i += TPB) sm[i] = g_x[i];
        for (int i = tid; i < H_SZ; i += TPB) sm[H_SZ + i] = h0[H_SZ + i];
        __syncthreads();

        const int gi = wid >> 3, jj = wid & 7;
        const int j = bid * 7 + jj;
        if (jj < 7 && j < H_SZ) {
            const int row = gi * H_SZ + j;
            const float4* a  = (const float4*)(Wih1 + (size_t)row * H_SZ);
            const float4* b  = (const float4*)(Whh1 + (size_t)row * H_SZ);
            const float4* x4 = (const float4*)sm;
            const float4* h4 = (const float4*)(sm + H_SZ);

            float s = 0.f;
            {
                float4 wv[8];
#pragma unroll
                for (int k = 0; k < 8; k++) wv[k] = a[lane + 32 * k];
#pragma unroll
                for (int k = 0; k < 8; k++) s += dot4(wv[k], x4[lane + 32 * k]);
            }
            {
                float4 wv[8];
#pragma unroll
                for (int k = 0; k < 8; k++) wv[k] = b[lane + 32 * k];
#pragma unroll
                for (int k = 0; k < 8; k++) s += dot4(wv[k], h4[lane + 32 * k]);
            }
            s = warp_sum(s);
            if (lane == 0) sm[2048 + gi * 8 + jj] = s + bih1[row] + bhh1[row];
        }
        __syncthreads();

        if (tid < 7) {
            const int jo = bid * 7 + tid;
            if (jo < H_SZ) {
                const float ig = sigf (sm[2048 + tid]);
                const float fg = sigf (sm[2048 + 8 + tid]);
                const float gg = tanhf(sm[2048 + 16 + tid]);
                const float og = sigf (sm[2048 + 24 + tid]);
                const float c = fg * c0[H_SZ + jo] + ig * gg;
                const float h = og * tanhf(c);
                c_new[H_SZ + jo] = c;
                h_new[H_SZ + jo] = h;
                g_q[jo] = h;
            }
        }
    }
    gbar();

    // ============ P3: u = W^T q (+ bq) — 384 fine units (≤3 per block) ===========
    {
        for (int i = tid; i < H_SZ; i += TPB) sm[i] = g_q[i];
        __syncthreads();
        const int col  = tid & 1;            // 2 f4 cols per unit
        const int rgrp = tid >> 1;           // 0..511
        float4* red = (float4*)(sm + 1024);  // 1024 float4

        for (int vb = bid; vb < 384; vb += NBLK) {
            const int hd = vb >> 7, chunk = vb & 127;
            const float* W    = (hd == 0) ? WL : (hd == 1) ? WR : WM;
            const float* bias = (hd == 0) ? bL : (hd == 1) ? bR : bM;
            const int c4 = chunk * 2 + col;  // f4 column (0..255)
            const float4* W4 = (const float4*)W;

            float4 w0 = W4[(size_t)rgrp * (C_SZ >> 2) + c4];
            float4 w1 = W4[(size_t)(rgrp + 512) * (C_SZ >> 2) + c4];
            const float q0 = sm[rgrp], q1 = sm[rgrp + 512];
            float4 acc;
            acc.x = w0.x * q0 + w1.x * q1;
            acc.y = w0.y * q0 + w1.y * q1;
            acc.z = w0.z * q0 + w1.z * q1;
            acc.w = w0.w * q0 + w1.w * q1;
            red[rgrp * 2 + col] = acc;
            __syncthreads();
#pragma unroll
            for (int sd = 256; sd >= 1; sd >>= 1) {
                if (rgrp < sd) {
                    float4 o = red[(rgrp + sd) * 2 + col];
                    float4 m = red[rgrp * 2 + col];
                    m.x += o.x; m.y += o.y; m.z += o.z; m.w += o.w;
                    red[rgrp * 2 + col] = m;
                }
                __syncthreads();
            }
            if (tid < 2) ((float4*)g_u[hd])[chunk * 2 + tid] = red[tid];

            if (chunk == 0) {   // bq = bias . q, fixed-order
                float v = bias[tid] * sm[tid];
                v = warp_sum(v);
                if (lane == 0) sm[5120 + wid] = v;
                __syncthreads();
                if (tid < 32) {
                    float tt = sm[5120 + tid];
                    tt = warp_sum(tt);
                    if (tid == 0) g_bq[hd] = tt;
                }
            }
            __syncthreads();
        }
    }
    gbar();

    // ============ P4: e[hd][s] = ctx[s,:]·u[hd] + bq[hd] (as in R6) ==============
    {
        for (int i = tid; i < 3 * C_SZ; i += TPB) sm[i] = ((const float*)g_u)[i];
        __syncthreads();
        for (int r = gw; r < 3 * S_SZ; r += NBLK * 32) {
            const int hd = r >> 11, srow = r & (S_SZ - 1);
            const float* ctx = (hd == 0) ? ctxL : (hd == 1) ? ctxR : ctxM;
            const float4* c4 = (const float4*)(ctx + (size_t)srow * C_SZ);
            const float4* u4 = (const float4*)(sm + hd * C_SZ);
            float4 wv[8];
#pragma unroll
            for (int k = 0; k < 8; k++) wv[k] = c4[lane + 32 * k];
            float s = 0.f;
#pragma unroll
            for (int k = 0; k < 8; k++) s += dot4(wv[k], u4[lane + 32 * k]);
            s = warp_sum(s);
            if (lane == 0) g_e[hd][srow] = s + g_bq[hd];
        }
    }
    gbar();

    // ============ P5: softmax (stats once) + wsum partials, 384 fine units =======
    {
        // stats per head, computed once per block (deterministic fixed order)
#pragma unroll
        for (int hd = 0; hd < 3; hd++) {
            const float e0 = g_e[hd][tid], e1 = g_e[hd][tid + 1024];
            float m = warp_max(fmaxf(e0, e1));
            if (lane == 0) sm[130 + wid] = m;
            __syncthreads();
            if (tid < 32) {
                float v = sm[130 + tid];
                v = warp_max(v);
                if (tid == 0) sm[164] = v;
            }
            __syncthreads();
            const float M = sm[164];
            float z = expf(e0 - M) + expf(e1 - M);
            z = warp_sum(z);
            __syncthreads();
            if (lane == 0) sm[130 + wid] = z;
            __syncthreads();
            if (tid < 32) {
                float v = sm[130 + tid];
                v = warp_sum(v);
                if (tid == 0) { sm[168 + hd] = M; sm[172 + hd] = 1.0f / v; }
            }
            __syncthreads();
        }

        float4* red4 = (float4*)(sm + 256);
        for (int vb = bid; vb < 384; vb += NBLK) {
            const int hd = vb >> 7, t = vb & 127;
            const int rc = t >> 3, cc = t & 7;      // 16 row chunks x 8 col chunks
            const float M = sm[168 + hd], inv = sm[172 + hd];
            if (tid < 128) sm[tid] = expf(g_e[hd][rc * 128 + tid] - M) * inv;
            __syncthreads();

            const float* ctx = (hd == 0) ? ctxL : (hd == 1) ? ctxR : ctxM;
            const float4* cp = (const float4*)ctx;
            const int c4col = cc * 32 + lane;
            float4 v[4];
#pragma unroll
            for (int k = 0; k < 4; k++)
                v[k] = cp[(size_t)(rc * 128 + wid + 32 * k) * (C_SZ >> 2) + c4col];
            float4 acc = make_float4(0.f, 0.f, 0.f, 0.f);
#pragma unroll
            for (int k = 0; k < 4; k++) {
                float av = sm[wid + 32 * k];
                acc.x += v[k].x * av; acc.y += v[k].y * av;
                acc.z += v[k].z * av; acc.w += v[k].w * av;
            }
            red4[wid * 32 + lane] = acc;
            __syncthreads();
#pragma unroll
            for (int sd = 16; sd >= 1; sd >>= 1) {
                if (wid < sd) {
                    float4 o = red4[(wid + sd) * 32 + lane];
                    float4 mm = red4[wid * 32 + lane];
                    mm.x += o.x; mm.y += o.y; mm.z += o.z; mm.w += o.w;
                    red4[wid * 32 + lane] = mm;
                }
                __syncthreads();
            }
            if (wid == 0) ((float4*)g_wpart[hd][rc])[cc * 32 + lane] = red4[lane];
            __syncthreads();
        }
    }
    gbar();

    // ============ P5b: reduce 16 partials -> g_ctx ===============================
    if (bid < 48 && tid < 64) {
        const int hd = bid >> 4, seg = bid & 15;
        const int c = seg * 64 + tid;
        float s = 0.f;
#pragma unroll
        for (int k = 0; k < NRC; k++) s += g_wpart[hd][k][c];
        g_ctx[hd][c] = s;
    }
    gbar();

    // ============ P6: concat GEMV — contiguous 7-row stripe per block ============
    {
        for (int i = tid; i < 4 * H_SZ; i += TPB)
            sm[i] = (i < H_SZ) ? g_q[i] : g_ctx[(i >> 10) - 1][i & (H_SZ - 1)];
        __syncthreads();

        const int rs = wid >> 2, seg = wid & 3;    // row slot 0..7 (7 used)
        const int row = bid * 7 + rs;
        if (rs < 7 && row < H_SZ) {
            const float4* a  = (const float4*)(Wc + (size_t)row * 4 * H_SZ + seg * H_SZ);
            const float4* x4 = (const float4*)(sm + seg * H_SZ);
            float4 wv[8];
#pragma unroll
            for (int k = 0; k < 8; k++) wv[k] = a[lane + 32 * k];
            float s = 0.f;
#pragma unroll
            for (int k = 0; k < 8; k++) s += dot4(wv[k], x4[lane + 32 * k]);
            s = warp_sum(s);
            if (lane == 0) sm[4200 + rs * 4 + seg] = s;
        }
        __syncthreads();
        if (tid < 7) {
            const int ro = bid * 7 + tid;
            if (ro < H_SZ) {
                const float t = sm[4200 + tid * 4] + sm[4200 + tid * 4 + 1] +
                                sm[4200 + tid * 4 + 2] + sm[4200 + tid * 4 + 3];
                g_co[ro] = tanhf(t + bc[ro]);
            }
        }
    }
    gbar();

    // ============ P7: output = Wo @ concat_out + bo (R6 structure, untouched) ====
    {
        if (tid < H_SZ) sm[tid] = g_co[tid];
        __syncthreads();
        const float4* x4 = (const float4*)sm;
        for (int r = gw; r < V_SZ; r += NBLK * 32) {
            const float4* a = (const float4*)(Wo + (size_t)r * H_SZ);
            float4 wv[8];
#pragma unroll
            for (int k = 0; k < 8; k++) wv[k] = a[lane + 32 * k];
            float s = 0.f;
#pragma unroll
            for (int k = 0; k < 8; k++) s += dot4(wv[k], x4[lane + 32 * k]);
            s = warp_sum(s);
            if (lane == 0) out[r] = s + bo[r];
        }
    }
}

// ==================================================================================
extern "C" void kernel_launch(void* const* d_in, const int* in_sizes, int n_in,
                              void* d_out, int out_size) {
    const int*   input_ids = (const int*)  d_in[0];
    const float* h0        = (const float*)d_in[1];
    const float* c0        = (const float*)d_in[2];
    const float* ctxL      = (const float*)d_in[3];
    const float* ctxR      = (const float*)d_in[4];
    const float* ctxM      = (const float*)d_in[5];
    const float* emb       = (const float*)d_in[6];
    const float* Wih0      = (const float*)d_in[7];
    const float* Whh0      = (const float*)d_in[8];
    const float* bih0      = (const float*)d_in[9];
    const float* bhh0      = (const float*)d_in[10];
    const float* Wih1      = (const float*)d_in[11];
    const float* Whh1      = (const float*)d_in[12];
    const float* bih1      = (const float*)d_in[13];
    const float* bhh1      = (const float*)d_in[14];
    const float* WL        = (const float*)d_in[15];
    const float* bL        = (const float*)d_in[16];
    const float* WR        = (const float*)d_in[17];
    const float* bR        = (const float*)d_in[18];
    const float* WM        = (const float*)d_in[19];
    const float* bM        = (const float*)d_in[20];
    const float* Wc        = (const float*)d_in[21];
    const float* bc        = (const float*)d_in[22];
    const float* Wo        = (const float*)d_in[23];
    const float* bo        = (const float*)d_in[24];

    float* out   = (float*)d_out;            // [V]
    float* h_new = out + V_SZ;               // [2*H]
    float* c_new = out + V_SZ + 2 * H_SZ;    // [2*H]

    megakernel<<<NBLK, TPB>>>(input_ids, h0, c0, ctxL, ctxR, ctxM, emb,
                              Wih0, Whh0, bih0, bhh0, Wih1, Whh1, bih1, bhh1,
                              WL, bL, WR, bR, WM, bM, Wc, bc, Wo, bo,
                              out, h_new, c_new);
}